// round 2
// baseline (speedup 1.0000x reference)
#include <cuda_runtime.h>
#include <cuda_bf16.h>
#include <cstdint>

// Problem constants (fixed by the dataset)
#define N_MAX   100000
#define E_MAX   1600000
#define ET_MAX  (N_MAX + E_MAX)
#define ROW     128        // xl(64) | xr(64) per node
#define HC      64         // HEADS * OUT_CH
#define OUTC    32

// -------- scratch (static device globals; no allocation) --------
__device__ __align__(128) float g_xlr[(size_t)N_MAX * ROW];     // 51.2 MB
__device__ __align__(128) float g_p[(size_t)ET_MAX * 2];        // 13.6 MB
__device__ __align__(128) float g_denom[(size_t)N_MAX * 2];
__device__ __align__(128) float g_inv[(size_t)N_MAX * 2];
__device__ __align__(128) float g_accum[(size_t)N_MAX * OUTC];  // 12.8 MB
__device__ int g_is64;   // 1 if edge_index is int64, 0 if int32

// ---------------- helpers ----------------
__device__ __forceinline__ unsigned long long pack_dup(float a) {
    unsigned int au = __float_as_uint(a);
    unsigned long long r;
    asm("mov.b64 %0, {%1, %1};" : "=l"(r) : "r"(au));
    return r;
}
__device__ __forceinline__ void unpack2(unsigned long long v, float& lo, float& hi) {
    unsigned int l, h;
    asm("mov.b64 {%0, %1}, %2;" : "=r"(l), "=r"(h) : "l"(v));
    lo = __uint_as_float(l); hi = __uint_as_float(h);
}
__device__ __forceinline__ void fma2(unsigned long long& acc, unsigned long long a, unsigned long long b) {
    asm("fma.rn.f32x2 %0, %1, %2, %0;" : "+l"(acc) : "l"(a), "l"(b));
}
__device__ __forceinline__ void red_add_v4(float* addr, float4 v) {
    asm volatile("red.global.add.v4.f32 [%0], {%1, %2, %3, %4};"
                 :: "l"(addr), "f"(v.x), "f"(v.y), "f"(v.z), "f"(v.w) : "memory");
}
__device__ __forceinline__ float lrelu(float x) { return (x > 0.f) ? x : 0.2f * x; }

// Load edge endpoints regardless of int32/int64 storage.
__device__ __forceinline__ void load_edge(const void* ei, int E, int ec, int& j, int& i) {
    if (g_is64) {
        const long long* p = (const long long*)ei;
        j = (int)p[ec]; i = (int)p[(size_t)E + ec];
    } else {
        const int* p = (const int*)ei;
        j = p[ec]; i = p[(size_t)E + ec];
    }
}

// ---------------- kernel D: detect edge_index dtype ----------------
__global__ void k_detect(const void* ei, int N) {
    const long long* p = (const long long*)ei;
    int ok = 1;
    #pragma unroll 1
    for (int t = 0; t < 64; t++) {
        long long v = p[t];
        if (v < 0 || v >= (long long)N) { ok = 0; break; }
    }
    g_is64 = ok;
}

// ---------------- kernel 0: zero accumulators ----------------
__global__ void k_zero(int N) {
    int idx = blockIdx.x * blockDim.x + threadIdx.x;
    if (idx < 2 * N) g_denom[idx] = 0.f;
    if (idx < OUTC * N) g_accum[idx] = 0.f;
}

// ---------------- kernel 1: xlr = x @ [Wl|Wr] + [bl|br] ----------------
// BM=64 rows, BN=128 (all) cols, BK=32.  256 threads.
__global__ void __launch_bounds__(256) k_gemm(
    const float* __restrict__ x, const float* __restrict__ Wl,
    const float* __restrict__ bl, const float* __restrict__ Wr,
    const float* __restrict__ br, int N)
{
    __shared__ __align__(16) float Xs_t[32][66];   // [kk][m]
    __shared__ __align__(16) float Ws[32][128];    // [kk][n]

    const int tid = threadIdx.x;
    const int tx = tid & 31;
    const int ty = tid >> 5;
    const int m0 = ty * 8;
    const int blockM = blockIdx.x * 64;

    unsigned long long acc[4][4];
    #pragma unroll
    for (int a = 0; a < 4; a++)
        #pragma unroll
        for (int b = 0; b < 4; b++) acc[a][b] = 0ull;

    for (int k0 = 0; k0 < 128; k0 += 32) {
        #pragma unroll
        for (int it = 0; it < 2; it++) {
            int t = tid + it * 256;          // 0..511
            int m = t >> 3;                  // 0..63
            int kkv = (t & 7) * 4;
            int gm = blockM + m;
            float4 v = make_float4(0.f, 0.f, 0.f, 0.f);
            if (gm < N) v = *reinterpret_cast<const float4*>(&x[(size_t)gm * 128 + k0 + kkv]);
            Xs_t[kkv + 0][m] = v.x;
            Xs_t[kkv + 1][m] = v.y;
            Xs_t[kkv + 2][m] = v.z;
            Xs_t[kkv + 3][m] = v.w;
        }
        #pragma unroll
        for (int it = 0; it < 4; it++) {
            int t = tid + it * 256;          // 0..1023
            int kk = t >> 5;                 // 0..31
            int n  = (t & 31) * 4;
            int gk = k0 + kk;
            float4 v = (n < 64)
                ? *reinterpret_cast<const float4*>(&Wl[(size_t)gk * 64 + n])
                : *reinterpret_cast<const float4*>(&Wr[(size_t)gk * 64 + (n - 64)]);
            *reinterpret_cast<float4*>(&Ws[kk][n]) = v;
        }
        __syncthreads();

        #pragma unroll
        for (int kk = 0; kk < 32; kk++) {
            unsigned long long apair[4];
            #pragma unroll
            for (int rp = 0; rp < 4; rp++)
                apair[rp] = *reinterpret_cast<const unsigned long long*>(&Xs_t[kk][m0 + 2 * rp]);
            #pragma unroll
            for (int jj = 0; jj < 4; jj++) {
                unsigned long long wp = pack_dup(Ws[kk][tx + 32 * jj]);
                #pragma unroll
                for (int rp = 0; rp < 4; rp++)
                    fma2(acc[rp][jj], apair[rp], wp);
            }
        }
        __syncthreads();
    }

    #pragma unroll
    for (int jj = 0; jj < 4; jj++) {
        int col = tx + 32 * jj;
        float bsum = (col < HC) ? bl[col] : br[col - HC];
        #pragma unroll
        for (int rp = 0; rp < 4; rp++) {
            float lo, hi;
            unpack2(acc[rp][jj], lo, hi);
            int gm = blockM + m0 + 2 * rp;
            if (gm < N)     g_xlr[(size_t)gm * ROW + col]       = lo + bsum;
            if (gm + 1 < N) g_xlr[(size_t)(gm + 1) * ROW + col] = hi + bsum;
        }
    }
}

// ---------------- kernel 2: edge scores p = exp(e), denom += p ----------------
// 8 lanes per edge. Lanes 0-3: head 0, lanes 4-7: head 1.
__global__ void __launch_bounds__(256) k_score(
    const void* __restrict__ ei, const float* __restrict__ att,
    int E, int N)
{
    int gid = blockIdx.x * blockDim.x + threadIdx.x;
    int e = gid >> 3;
    int l = gid & 7;
    int Etot = E + N;
    bool valid = (e < Etot);
    int ec = valid ? e : (Etot - 1);

    int j, i;
    if (ec < E) load_edge(ei, E, ec, j, i);
    else        j = i = ec - E;

    const float4* xlj = reinterpret_cast<const float4*>(g_xlr + (size_t)j * ROW);       // xl
    const float4* xri = reinterpret_cast<const float4*>(g_xlr + (size_t)i * ROW + HC);  // xr
    const float4* at4 = reinterpret_cast<const float4*>(att);

    float4 a0 = xlj[2 * l],     a1 = xlj[2 * l + 1];
    float4 b0 = xri[2 * l],     b1 = xri[2 * l + 1];
    float4 t0 = at4[2 * l],     t1 = at4[2 * l + 1];

    float s = 0.f;
    s += t0.x * lrelu(a0.x + b0.x);
    s += t0.y * lrelu(a0.y + b0.y);
    s += t0.z * lrelu(a0.z + b0.z);
    s += t0.w * lrelu(a0.w + b0.w);
    s += t1.x * lrelu(a1.x + b1.x);
    s += t1.y * lrelu(a1.y + b1.y);
    s += t1.z * lrelu(a1.z + b1.z);
    s += t1.w * lrelu(a1.w + b1.w);

    s += __shfl_xor_sync(0xffffffffu, s, 1);
    s += __shfl_xor_sync(0xffffffffu, s, 2);

    if (valid && (l & 3) == 0) {
        int h = l >> 2;
        float pv = expf(s);   // segment-softmax without max shift (identical result)
        g_p[2 * (size_t)ec + h] = pv;
        atomicAdd(&g_denom[2 * (size_t)i + h], pv);
    }
}

// ---------------- kernel 3: inv denom ----------------
__global__ void k_inv(int N) {
    int idx = blockIdx.x * blockDim.x + threadIdx.x;
    if (idx < 2 * N) g_inv[idx] = 1.f / (g_denom[idx] + 1e-16f);
}

// ---------------- kernel 4: weighted scatter-add (head mean folded in) ----------------
__global__ void __launch_bounds__(256) k_agg(
    const void* __restrict__ ei, int E, int N)
{
    int gid = blockIdx.x * blockDim.x + threadIdx.x;
    int e = gid >> 3;
    int l = gid & 7;
    int Etot = E + N;
    if (e >= Etot) return;

    int j, i;
    if (e < E) load_edge(ei, E, e, j, i);
    else       j = i = e - E;

    float2 pv = *reinterpret_cast<const float2*>(&g_p[2 * (size_t)e]);
    float2 iv = *reinterpret_cast<const float2*>(&g_inv[2 * (size_t)i]);
    float a0 = pv.x * iv.x * 0.5f;   // 0.5 = head mean
    float a1 = pv.y * iv.y * 0.5f;

    const float4* xlj = reinterpret_cast<const float4*>(g_xlr + (size_t)j * ROW);
    float4 v0 = xlj[l];        // head 0, ch 4l..4l+3
    float4 v1 = xlj[8 + l];    // head 1, ch 4l..4l+3

    float4 c;
    c.x = a0 * v0.x + a1 * v1.x;
    c.y = a0 * v0.y + a1 * v1.y;
    c.z = a0 * v0.z + a1 * v1.z;
    c.w = a0 * v0.w + a1 * v1.w;

    red_add_v4(&g_accum[(size_t)i * OUTC + 4 * l], c);
}

// ---------------- kernel 5: bias + silu ----------------
__global__ void k_final(const float* __restrict__ bias, float* __restrict__ out, int N) {
    int idx = blockIdx.x * blockDim.x + threadIdx.x;
    if (idx < N * OUTC) {
        float v = g_accum[idx] + bias[idx & (OUTC - 1)];
        out[idx] = v / (1.f + expf(-v));
    }
}

// ---------------- launch ----------------
extern "C" void kernel_launch(void* const* d_in, const int* in_sizes, int n_in,
                              void* d_out, int out_size) {
    const float* x    = (const float*)d_in[0];
    const float* Wl   = (const float*)d_in[1];
    const float* bl   = (const float*)d_in[2];
    const float* Wr   = (const float*)d_in[3];
    const float* br   = (const float*)d_in[4];
    const float* att  = (const float*)d_in[5];
    const float* bias = (const float*)d_in[6];
    const void*  ei   = (const void*)d_in[7];
    float* out = (float*)d_out;

    int N = in_sizes[0] / 128;   // 100000
    int E = in_sizes[7] / 2;     // 1600000
    int Etot = E + N;

    k_detect<<<1, 1>>>(ei, N);
    k_zero<<<(OUTC * N + 255) / 256, 256>>>(N);
    k_gemm<<<(N + 63) / 64, 256>>>(x, Wl, bl, Wr, br, N);
    k_score<<<(Etot * 8 + 255) / 256, 256>>>(ei, att, E, N);
    k_inv<<<(2 * N + 255) / 256, 256>>>(N);
    k_agg<<<(Etot * 8 + 255) / 256, 256>>>(ei, E, N);
    k_final<<<(OUTC * N + 255) / 256, 256>>>(bias, out, N);
}

// round 3
// speedup vs baseline: 1.0044x; 1.0044x over previous
#include <cuda_runtime.h>
#include <cuda_bf16.h>
#include <cstdint>

// Problem constants (fixed by the dataset)
#define N_MAX   100000
#define E_MAX   1600000
#define ET_MAX  (N_MAX + E_MAX)
#define ROW     128        // xl(64) | xr(64) per node
#define HC      64         // HEADS * OUT_CH
#define OUTC    32

// -------- scratch (static device globals; no allocation) --------
__device__ __align__(128) float g_xlr[(size_t)N_MAX * ROW];     // 51.2 MB
__device__ __align__(128) float g_denom[(size_t)N_MAX * 2];
__device__ __align__(128) float g_accum[(size_t)N_MAX * HC];    // [n][h][c] 25.6 MB
__device__ int g_is64;   // 1 if edge_index is int64, 0 if int32

// ---------------- helpers ----------------
__device__ __forceinline__ unsigned long long pack_dup(float a) {
    unsigned int au = __float_as_uint(a);
    unsigned long long r;
    asm("mov.b64 %0, {%1, %1};" : "=l"(r) : "r"(au));
    return r;
}
__device__ __forceinline__ void unpack2(unsigned long long v, float& lo, float& hi) {
    unsigned int l, h;
    asm("mov.b64 {%0, %1}, %2;" : "=r"(l), "=r"(h) : "l"(v));
    lo = __uint_as_float(l); hi = __uint_as_float(h);
}
__device__ __forceinline__ void fma2(unsigned long long& acc, unsigned long long a, unsigned long long b) {
    asm("fma.rn.f32x2 %0, %1, %2, %0;" : "+l"(acc) : "l"(a), "l"(b));
}
__device__ __forceinline__ void red_add_v4(float* addr, float4 v) {
    asm volatile("red.global.add.v4.f32 [%0], {%1, %2, %3, %4};"
                 :: "l"(addr), "f"(v.x), "f"(v.y), "f"(v.z), "f"(v.w) : "memory");
}
__device__ __forceinline__ float lrelu(float x) { return (x > 0.f) ? x : 0.2f * x; }

__device__ __forceinline__ void load_edge(const void* ei, int E, int ec, int& j, int& i) {
    if (g_is64) {
        const long long* p = (const long long*)ei;
        j = (int)p[ec]; i = (int)p[(size_t)E + ec];
    } else {
        const int* p = (const int*)ei;
        j = p[ec]; i = p[(size_t)E + ec];
    }
}

// ---------------- kernel D: detect edge_index dtype ----------------
__global__ void k_detect(const void* ei, int N) {
    const long long* p = (const long long*)ei;
    int ok = 1;
    #pragma unroll 1
    for (int t = 0; t < 64; t++) {
        long long v = p[t];
        if (v < 0 || v >= (long long)N) { ok = 0; break; }
    }
    g_is64 = ok;
}

// ---------------- kernel 0: zero accumulators ----------------
__global__ void k_zero(int N) {
    int idx = blockIdx.x * blockDim.x + threadIdx.x;
    if (idx < 16 * N) reinterpret_cast<float4*>(g_accum)[idx] = make_float4(0.f, 0.f, 0.f, 0.f);
    if (idx < 2 * N)  g_denom[idx] = 0.f;
}

// ---------------- kernel 1: xlr = x @ [Wl|Wr] + [bl|br] ----------------
// BM=64 rows, BN=128 (all) cols, BK=32.  256 threads, f32x2 packed FMA.
__global__ void __launch_bounds__(256) k_gemm(
    const float* __restrict__ x, const float* __restrict__ Wl,
    const float* __restrict__ bl, const float* __restrict__ Wr,
    const float* __restrict__ br, int N)
{
    __shared__ __align__(16) float Xs_t[32][66];   // [kk][m]
    __shared__ __align__(16) float Ws[32][128];    // [kk][n]

    const int tid = threadIdx.x;
    const int tx = tid & 31;
    const int ty = tid >> 5;
    const int m0 = ty * 8;
    const int blockM = blockIdx.x * 64;

    unsigned long long acc[4][4];
    #pragma unroll
    for (int a = 0; a < 4; a++)
        #pragma unroll
        for (int b = 0; b < 4; b++) acc[a][b] = 0ull;

    for (int k0 = 0; k0 < 128; k0 += 32) {
        #pragma unroll
        for (int it = 0; it < 2; it++) {
            int t = tid + it * 256;          // 0..511
            int m = t >> 3;                  // 0..63
            int kkv = (t & 7) * 4;
            int gm = blockM + m;
            float4 v = make_float4(0.f, 0.f, 0.f, 0.f);
            if (gm < N) v = *reinterpret_cast<const float4*>(&x[(size_t)gm * 128 + k0 + kkv]);
            Xs_t[kkv + 0][m] = v.x;
            Xs_t[kkv + 1][m] = v.y;
            Xs_t[kkv + 2][m] = v.z;
            Xs_t[kkv + 3][m] = v.w;
        }
        #pragma unroll
        for (int it = 0; it < 4; it++) {
            int t = tid + it * 256;          // 0..1023
            int kk = t >> 5;                 // 0..31
            int n  = (t & 31) * 4;
            int gk = k0 + kk;
            float4 v = (n < 64)
                ? *reinterpret_cast<const float4*>(&Wl[(size_t)gk * 64 + n])
                : *reinterpret_cast<const float4*>(&Wr[(size_t)gk * 64 + (n - 64)]);
            *reinterpret_cast<float4*>(&Ws[kk][n]) = v;
        }
        __syncthreads();

        #pragma unroll
        for (int kk = 0; kk < 32; kk++) {
            unsigned long long apair[4];
            #pragma unroll
            for (int rp = 0; rp < 4; rp++)
                apair[rp] = *reinterpret_cast<const unsigned long long*>(&Xs_t[kk][m0 + 2 * rp]);
            #pragma unroll
            for (int jj = 0; jj < 4; jj++) {
                unsigned long long wp = pack_dup(Ws[kk][tx + 32 * jj]);
                #pragma unroll
                for (int rp = 0; rp < 4; rp++)
                    fma2(acc[rp][jj], apair[rp], wp);
            }
        }
        __syncthreads();
    }

    #pragma unroll
    for (int jj = 0; jj < 4; jj++) {
        int col = tx + 32 * jj;
        float bsum = (col < HC) ? bl[col] : br[col - HC];
        #pragma unroll
        for (int rp = 0; rp < 4; rp++) {
            float lo, hi;
            unpack2(acc[rp][jj], lo, hi);
            int gm = blockM + m0 + 2 * rp;
            if (gm < N)     g_xlr[(size_t)gm * ROW + col]       = lo + bsum;
            if (gm + 1 < N) g_xlr[(size_t)(gm + 1) * ROW + col] = hi + bsum;
        }
    }
}

// ---------------- kernel 2: FUSED edge pass ----------------
// For each edge (j -> i):
//   p_h  = exp( att_h . lrelu(xl[j,h,:] + xr[i,h,:]) )
//   denom[i,h]      += p_h
//   accum[i,h,:]    += p_h * xl[j,h,:]
// (normalization deferred to epilogue; mathematically identical to softmax)
// 8 lanes per edge. Lane l holds floats 8l..8l+7 (lanes 0-3 = head 0, 4-7 = head 1).
__global__ void __launch_bounds__(256) k_edge(
    const void* __restrict__ ei, const float* __restrict__ att,
    int E, int N)
{
    int gid = blockIdx.x * blockDim.x + threadIdx.x;
    int e = gid >> 3;
    int l = gid & 7;
    int Etot = E + N;
    bool valid = (e < Etot);
    int ec = valid ? e : (Etot - 1);

    int j, i;
    if (ec < E) load_edge(ei, E, ec, j, i);
    else        j = i = ec - E;

    const float4* xlj = reinterpret_cast<const float4*>(g_xlr + (size_t)j * ROW);       // xl
    const float4* xri = reinterpret_cast<const float4*>(g_xlr + (size_t)i * ROW + HC);  // xr
    const float4* at4 = reinterpret_cast<const float4*>(att);

    float4 a0 = xlj[2 * l],     a1 = xlj[2 * l + 1];
    float4 b0 = xri[2 * l],     b1 = xri[2 * l + 1];
    float4 t0 = at4[2 * l],     t1 = at4[2 * l + 1];

    float s = 0.f;
    s += t0.x * lrelu(a0.x + b0.x);
    s += t0.y * lrelu(a0.y + b0.y);
    s += t0.z * lrelu(a0.z + b0.z);
    s += t0.w * lrelu(a0.w + b0.w);
    s += t1.x * lrelu(a1.x + b1.x);
    s += t1.y * lrelu(a1.y + b1.y);
    s += t1.z * lrelu(a1.z + b1.z);
    s += t1.w * lrelu(a1.w + b1.w);

    // full head-sum lands in every lane of the 4-lane group
    s += __shfl_xor_sync(0xffffffffu, s, 1);
    s += __shfl_xor_sync(0xffffffffu, s, 2);

    float p = expf(s);   // own-head softmax numerator

    if (valid) {
        if ((l & 3) == 0) {
            int h = l >> 2;
            atomicAdd(&g_denom[2 * (size_t)i + h], p);
        }
        // contribution p * xl[j] for this lane's 8 floats (its own head)
        float4 c0, c1;
        c0.x = p * a0.x; c0.y = p * a0.y; c0.z = p * a0.z; c0.w = p * a0.w;
        c1.x = p * a1.x; c1.y = p * a1.y; c1.z = p * a1.z; c1.w = p * a1.w;
        float* dst = &g_accum[(size_t)i * HC + 8 * l];
        red_add_v4(dst,     c0);
        red_add_v4(dst + 4, c1);
    }
}

// ---------------- kernel 3: normalize + head mean + bias + silu ----------------
__global__ void k_final(const float* __restrict__ bias, float* __restrict__ out, int N) {
    int idx = blockIdx.x * blockDim.x + threadIdx.x;   // n*32 + c
    if (idx < N * OUTC) {
        int n = idx >> 5;
        int c = idx & 31;
        float2 d = *reinterpret_cast<const float2*>(&g_denom[2 * (size_t)n]);
        float v0 = g_accum[(size_t)n * HC + c]        / (d.x + 1e-16f);
        float v1 = g_accum[(size_t)n * HC + 32 + c]   / (d.y + 1e-16f);
        float v = 0.5f * (v0 + v1) + bias[c];
        out[idx] = v / (1.f + expf(-v));
    }
}

// ---------------- launch ----------------
extern "C" void kernel_launch(void* const* d_in, const int* in_sizes, int n_in,
                              void* d_out, int out_size) {
    const float* x    = (const float*)d_in[0];
    const float* Wl   = (const float*)d_in[1];
    const float* bl   = (const float*)d_in[2];
    const float* Wr   = (const float*)d_in[3];
    const float* br   = (const float*)d_in[4];
    const float* att  = (const float*)d_in[5];
    const float* bias = (const float*)d_in[6];
    const void*  ei   = (const void*)d_in[7];
    float* out = (float*)d_out;

    int N = in_sizes[0] / 128;   // 100000
    int E = in_sizes[7] / 2;     // 1600000
    int Etot = E + N;

    k_detect<<<1, 1>>>(ei, N);
    k_zero<<<(16 * N + 255) / 256, 256>>>(N);
    k_gemm<<<(N + 63) / 64, 256>>>(x, Wl, bl, Wr, br, N);
    k_edge<<<(Etot * 8 + 255) / 256, 256>>>(ei, att, E, N);
    k_final<<<(OUTC * N + 255) / 256, 256>>>(bias, out, N);
}

// round 4
// speedup vs baseline: 1.1542x; 1.1492x over previous
#include <cuda_runtime.h>
#include <cuda_fp16.h>
#include <cstdint>

// Problem constants (fixed by the dataset)
#define N_MAX   100000
#define E_MAX   1600000
#define ET_MAX  (N_MAX + E_MAX)
#define ROW     128        // xl(64) | xr(64) per node
#define HC      64         // HEADS * OUT_CH
#define OUTC    32

// -------- scratch (static device globals; no allocation) --------
__device__ __align__(128) __half g_xlr[(size_t)N_MAX * ROW];    // 25.6 MB (fp16)
__device__ __align__(128) float g_denom[(size_t)N_MAX * 2];
__device__ __align__(128) float g_accum[(size_t)N_MAX * HC];    // [n][h][c] 25.6 MB
__device__ int g_is64;   // 1 if edge_index is int64, 0 if int32

// ---------------- helpers ----------------
__device__ __forceinline__ unsigned long long pack_dup(float a) {
    unsigned int au = __float_as_uint(a);
    unsigned long long r;
    asm("mov.b64 %0, {%1, %1};" : "=l"(r) : "r"(au));
    return r;
}
__device__ __forceinline__ void unpack2(unsigned long long v, float& lo, float& hi) {
    unsigned int l, h;
    asm("mov.b64 {%0, %1}, %2;" : "=r"(l), "=r"(h) : "l"(v));
    lo = __uint_as_float(l); hi = __uint_as_float(h);
}
__device__ __forceinline__ void fma2(unsigned long long& acc, unsigned long long a, unsigned long long b) {
    asm("fma.rn.f32x2 %0, %1, %2, %0;" : "+l"(acc) : "l"(a), "l"(b));
}
__device__ __forceinline__ void red_add_v4(float* addr, float4 v) {
    asm volatile("red.global.add.v4.f32 [%0], {%1, %2, %3, %4};"
                 :: "l"(addr), "f"(v.x), "f"(v.y), "f"(v.z), "f"(v.w) : "memory");
}
__device__ __forceinline__ float lrelu(float x) { return (x > 0.f) ? x : 0.2f * x; }

__device__ __forceinline__ void load_edge(const void* ei, int E, int ec, int& j, int& i) {
    if (g_is64) {
        const long long* p = (const long long*)ei;
        j = (int)p[ec]; i = (int)p[(size_t)E + ec];
    } else {
        const int* p = (const int*)ei;
        j = p[ec]; i = p[(size_t)E + ec];
    }
}

// ---------------- kernel D: detect edge_index dtype ----------------
__global__ void k_detect(const void* ei, int N) {
    const long long* p = (const long long*)ei;
    int ok = 1;
    #pragma unroll 1
    for (int t = 0; t < 64; t++) {
        long long v = p[t];
        if (v < 0 || v >= (long long)N) { ok = 0; break; }
    }
    g_is64 = ok;
}

// ---------------- kernel 1: xlr = fp16( x @ [Wl|Wr] + [bl|br] ) ----------------
// BM=64 rows, BN=128 (all) cols, BK=32.  256 threads, f32x2 packed FMA.
// Also zeroes this block's slice of g_accum / g_denom (removes separate k_zero).
__global__ void __launch_bounds__(256) k_gemm(
    const float* __restrict__ x, const float* __restrict__ Wl,
    const float* __restrict__ bl, const float* __restrict__ Wr,
    const float* __restrict__ br, int N)
{
    __shared__ __align__(16) float Xs_t[32][66];   // [kk][m]
    __shared__ __align__(16) float Ws[32][128];    // [kk][n]

    const int tid = threadIdx.x;
    const int tx = tid & 31;
    const int ty = tid >> 5;
    const int m0 = ty * 8;
    const int blockM = blockIdx.x * 64;

    // ---- zero accum/denom slice for rows [blockM, blockM+64) ----
    {
        const float4 z = make_float4(0.f, 0.f, 0.f, 0.f);
        // accum: 64 rows * 64 floats = 1024 float4
        float4* ab = reinterpret_cast<float4*>(&g_accum[(size_t)blockM * HC]);
        size_t lim = (size_t)(N - blockM) * (HC / 4);   // guard last block
        #pragma unroll
        for (int it = 0; it < 4; it++) {
            size_t idx = tid + it * 256;
            if (idx < 1024 && idx < lim) ab[idx] = z;
        }
        if (tid < 128 && blockM + (tid >> 1) < N) g_denom[2 * (size_t)blockM + tid] = 0.f;
    }

    unsigned long long acc[4][4];
    #pragma unroll
    for (int a = 0; a < 4; a++)
        #pragma unroll
        for (int b = 0; b < 4; b++) acc[a][b] = 0ull;

    for (int k0 = 0; k0 < 128; k0 += 32) {
        #pragma unroll
        for (int it = 0; it < 2; it++) {
            int t = tid + it * 256;          // 0..511
            int m = t >> 3;                  // 0..63
            int kkv = (t & 7) * 4;
            int gm = blockM + m;
            float4 v = make_float4(0.f, 0.f, 0.f, 0.f);
            if (gm < N) v = *reinterpret_cast<const float4*>(&x[(size_t)gm * 128 + k0 + kkv]);
            Xs_t[kkv + 0][m] = v.x;
            Xs_t[kkv + 1][m] = v.y;
            Xs_t[kkv + 2][m] = v.z;
            Xs_t[kkv + 3][m] = v.w;
        }
        #pragma unroll
        for (int it = 0; it < 4; it++) {
            int t = tid + it * 256;          // 0..1023
            int kk = t >> 5;                 // 0..31
            int n  = (t & 31) * 4;
            int gk = k0 + kk;
            float4 v = (n < 64)
                ? *reinterpret_cast<const float4*>(&Wl[(size_t)gk * 64 + n])
                : *reinterpret_cast<const float4*>(&Wr[(size_t)gk * 64 + (n - 64)]);
            *reinterpret_cast<float4*>(&Ws[kk][n]) = v;
        }
        __syncthreads();

        #pragma unroll
        for (int kk = 0; kk < 32; kk++) {
            unsigned long long apair[4];
            #pragma unroll
            for (int rp = 0; rp < 4; rp++)
                apair[rp] = *reinterpret_cast<const unsigned long long*>(&Xs_t[kk][m0 + 2 * rp]);
            #pragma unroll
            for (int jj = 0; jj < 4; jj++) {
                unsigned long long wp = pack_dup(Ws[kk][tx + 32 * jj]);
                #pragma unroll
                for (int rp = 0; rp < 4; rp++)
                    fma2(acc[rp][jj], apair[rp], wp);
            }
        }
        __syncthreads();
    }

    #pragma unroll
    for (int jj = 0; jj < 4; jj++) {
        int col = tx + 32 * jj;
        float bsum = (col < HC) ? bl[col] : br[col - HC];
        #pragma unroll
        for (int rp = 0; rp < 4; rp++) {
            float lo, hi;
            unpack2(acc[rp][jj], lo, hi);
            int gm = blockM + m0 + 2 * rp;
            if (gm < N)     g_xlr[(size_t)gm * ROW + col]       = __float2half_rn(lo + bsum);
            if (gm + 1 < N) g_xlr[(size_t)(gm + 1) * ROW + col] = __float2half_rn(hi + bsum);
        }
    }
}

// ---------------- kernel 2: FUSED edge pass (fp16 gathers) ----------------
// For each edge (j -> i):
//   p_h  = exp( att_h . lrelu(xl[j,h,:] + xr[i,h,:]) )
//   denom[i,h]   += p_h
//   accum[i,h,:] += p_h * xl[j,h,:]
// 8 lanes per edge. Lane l holds channels 8l..8l+7 (lanes 0-3 head 0, 4-7 head 1).
__global__ void __launch_bounds__(256) k_edge(
    const void* __restrict__ ei, const float* __restrict__ att,
    int E, int N)
{
    int gid = blockIdx.x * blockDim.x + threadIdx.x;
    int e = gid >> 3;
    int l = gid & 7;
    int Etot = E + N;
    bool valid = (e < Etot);
    int ec = valid ? e : (Etot - 1);

    int j, i;
    if (ec < E) load_edge(ei, E, ec, j, i);
    else        j = i = ec - E;

    // one 16B load each: 8 halves of xl[j] and xr[i] for this lane
    uint4 va = *reinterpret_cast<const uint4*>(g_xlr + (size_t)j * ROW + 8 * l);
    uint4 vb = *reinterpret_cast<const uint4*>(g_xlr + (size_t)i * ROW + HC + 8 * l);

    const __half2* ha = reinterpret_cast<const __half2*>(&va);
    const __half2* hb = reinterpret_cast<const __half2*>(&vb);

    float2 a[4], b[4];
    #pragma unroll
    for (int q = 0; q < 4; q++) { a[q] = __half22float2(ha[q]); b[q] = __half22float2(hb[q]); }

    const float4* at4 = reinterpret_cast<const float4*>(att);
    float4 t0 = at4[2 * l], t1 = at4[2 * l + 1];
    const float* tt = &t0.x;   // t0,t1 contiguous in regs? safer: explicit

    float s = 0.f;
    s += t0.x * lrelu(a[0].x + b[0].x);
    s += t0.y * lrelu(a[0].y + b[0].y);
    s += t0.z * lrelu(a[1].x + b[1].x);
    s += t0.w * lrelu(a[1].y + b[1].y);
    s += t1.x * lrelu(a[2].x + b[2].x);
    s += t1.y * lrelu(a[2].y + b[2].y);
    s += t1.z * lrelu(a[3].x + b[3].x);
    s += t1.w * lrelu(a[3].y + b[3].y);
    (void)tt;

    // full head-sum lands in every lane of the 4-lane group
    s += __shfl_xor_sync(0xffffffffu, s, 1);
    s += __shfl_xor_sync(0xffffffffu, s, 2);

    float p = expf(s);   // own-head softmax numerator (max-shift-free; identical result)

    if (valid) {
        if ((l & 3) == 0) {
            int h = l >> 2;
            atomicAdd(&g_denom[2 * (size_t)i + h], p);
        }
        float4 c0, c1;
        c0.x = p * a[0].x; c0.y = p * a[0].y; c0.z = p * a[1].x; c0.w = p * a[1].y;
        c1.x = p * a[2].x; c1.y = p * a[2].y; c1.z = p * a[3].x; c1.w = p * a[3].y;
        float* dst = &g_accum[(size_t)i * HC + 8 * l];
        red_add_v4(dst,     c0);
        red_add_v4(dst + 4, c1);
    }
}

// ---------------- kernel 3: normalize + head mean + bias + silu ----------------
__global__ void k_final(const float* __restrict__ bias, float* __restrict__ out, int N) {
    int idx = blockIdx.x * blockDim.x + threadIdx.x;   // n*32 + c
    if (idx < N * OUTC) {
        int n = idx >> 5;
        int c = idx & 31;
        float2 d = *reinterpret_cast<const float2*>(&g_denom[2 * (size_t)n]);
        float v0 = g_accum[(size_t)n * HC + c]      / (d.x + 1e-16f);
        float v1 = g_accum[(size_t)n * HC + 32 + c] / (d.y + 1e-16f);
        float v = 0.5f * (v0 + v1) + bias[c];
        out[idx] = v / (1.f + expf(-v));
    }
}

// ---------------- launch ----------------
extern "C" void kernel_launch(void* const* d_in, const int* in_sizes, int n_in,
                              void* d_out, int out_size) {
    const float* x    = (const float*)d_in[0];
    const float* Wl   = (const float*)d_in[1];
    const float* bl   = (const float*)d_in[2];
    const float* Wr   = (const float*)d_in[3];
    const float* br   = (const float*)d_in[4];
    const float* att  = (const float*)d_in[5];
    const float* bias = (const float*)d_in[6];
    const void*  ei   = (const void*)d_in[7];
    float* out = (float*)d_out;

    int N = in_sizes[0] / 128;   // 100000
    int E = in_sizes[7] / 2;     // 1600000
    int Etot = E + N;

    k_detect<<<1, 1>>>(ei, N);
    k_gemm<<<(N + 63) / 64, 256>>>(x, Wl, bl, Wr, br, N);
    k_edge<<<(Etot * 8 + 255) / 256, 256>>>(ei, att, E, N);
    k_final<<<(OUTC * N + 255) / 256, 256>>>(bias, out, N);
}